// round 4
// baseline (speedup 1.0000x reference)
#include <cuda_runtime.h>
#include <cstdint>

// Masked mean over first xs_len[b] rows of xs[b]: out[b][d] = sum_{s<L} xs[b][s][d] / L
// xs: [16, 4096, 512] f32, xs_len: [16] (int32 OR int64 -- decoded at runtime), out: [16, 512] f32

#define B 16
#define S 4096
#define D 512
#define D4 (D / 4)          // 128 float4 per row
#define SPLIT 64
#define ROWS_PER_SPLIT (S / SPLIT)   // 64

// Deterministic scratch for partial sums: [B][SPLIT][D] floats = 2 MiB.
// Fully written by every K1 launch (zero partials included), so no init needed.
__device__ float4 g_partial[B * SPLIT * D4];

// Robust length decode: if the buffer is int64, ll[b] is in [1, S].
// If it is int32, ll[b] packs two lengths (both >= 1), so it exceeds 2^32
// and is out of range -> fall back to int32 read. Per-b decision, sound
// because lengths are in [1, 4096] and never 0.
__device__ __forceinline__ int decode_len(const void* xs_len, int b) {
    long long v64 = ((const long long*)xs_len)[b];
    if (v64 >= 1 && v64 <= (long long)S) return (int)v64;
    return ((const int*)xs_len)[b];
}

__global__ void __launch_bounds__(D4, 8)
mean_partial_kernel(const float* __restrict__ xs,
                    const void* __restrict__ xs_len) {
    const int sp = blockIdx.x;          // split index  [0, SPLIT)
    const int b  = blockIdx.y;          // batch index  [0, B)
    const int t  = threadIdx.x;         // float4 column [0, D4)

    const int L = decode_len(xs_len, b);
    int s0 = sp * ROWS_PER_SPLIT;
    int s1 = s0 + ROWS_PER_SPLIT;
    if (s1 > L) s1 = L;

    const float4* __restrict__ base =
        reinterpret_cast<const float4*>(xs + (size_t)b * S * D) + t;

    float4 acc = make_float4(0.f, 0.f, 0.f, 0.f);

    int s = s0;
    // Unrolled by 4 for MLP (keeps >= 4 independent 16B loads in flight per thread)
    for (; s + 4 <= s1; s += 4) {
        float4 v0 = base[(size_t)(s + 0) * D4];
        float4 v1 = base[(size_t)(s + 1) * D4];
        float4 v2 = base[(size_t)(s + 2) * D4];
        float4 v3 = base[(size_t)(s + 3) * D4];
        acc.x += v0.x + v1.x; acc.y += v0.y + v1.y;
        acc.z += v0.z + v1.z; acc.w += v0.w + v1.w;
        acc.x += v2.x + v3.x; acc.y += v2.y + v3.y;
        acc.z += v2.z + v3.z; acc.w += v2.w + v3.w;
    }
    for (; s < s1; s++) {
        float4 v = base[(size_t)s * D4];
        acc.x += v.x; acc.y += v.y; acc.z += v.z; acc.w += v.w;
    }

    g_partial[(b * SPLIT + sp) * D4 + t] = acc;
}

__global__ void __launch_bounds__(D4)
mean_finalize_kernel(const void* __restrict__ xs_len,
                     float* __restrict__ out) {
    const int b = blockIdx.x;
    const int t = threadIdx.x;

    float4 acc = make_float4(0.f, 0.f, 0.f, 0.f);
#pragma unroll
    for (int sp = 0; sp < SPLIT; sp++) {
        float4 v = g_partial[(b * SPLIT + sp) * D4 + t];
        acc.x += v.x; acc.y += v.y; acc.z += v.z; acc.w += v.w;
    }

    const float inv = 1.0f / (float)decode_len(xs_len, b);
    float4 r = make_float4(acc.x * inv, acc.y * inv, acc.z * inv, acc.w * inv);
    reinterpret_cast<float4*>(out)[b * D4 + t] = r;
}

extern "C" void kernel_launch(void* const* d_in, const int* in_sizes, int n_in,
                              void* d_out, int out_size) {
    const float* xs = (const float*)d_in[0];
    const void* xs_len = d_in[1];
    float* out = (float*)d_out;

    dim3 grid1(SPLIT, B);
    mean_partial_kernel<<<grid1, D4>>>(xs, xs_len);
    mean_finalize_kernel<<<B, D4>>>(xs_len, out);
}

// round 5
// speedup vs baseline: 1.2314x; 1.2314x over previous
#include <cuda_runtime.h>
#include <cstdint>

// Masked mean over first xs_len[b] rows of xs[b]: out[b][d] = sum_{s<L} xs[b][s][d] / L
// xs: [16, 4096, 512] f32, xs_len: [16] (int32 OR int64 -- decoded at runtime), out: [16, 512] f32

#define B 16
#define S 4096
#define D 512
#define D4 (D / 4)                   // 128 float4 per row
#define SPLIT 64
#define ROWS_PER_SPLIT (S / SPLIT)   // 64

// Deterministic scratch for partial sums: [B][SPLIT][D] floats = 2 MiB.
// Fully written by every K1 launch (zero partials included), so no init needed.
__device__ float4 g_partial[B * SPLIT * D4];

// Robust length decode: if the buffer is int64, value is in [1, S].
// If it is int32, the 64-bit read packs two lengths (both >= 1) and falls
// outside [1, S] -> fall back to the int32 read.
__device__ __forceinline__ int decode_len(const void* xs_len, int b) {
    long long v64 = ((const long long*)xs_len)[b];
    if (v64 >= 1 && v64 <= (long long)S) return (int)v64;
    return ((const int*)xs_len)[b];
}

__global__ void __launch_bounds__(D4, 8)
mean_partial_kernel(const float* __restrict__ xs,
                    const void* __restrict__ xs_len) {
    const int sp = blockIdx.x;          // split index  [0, SPLIT)
    const int b  = blockIdx.y;          // batch index  [0, B)
    const int t  = threadIdx.x;         // float4 column [0, D4)

    const int L = decode_len(xs_len, b);
    int s0 = sp * ROWS_PER_SPLIT;
    int s1 = s0 + ROWS_PER_SPLIT;
    if (s1 > L) s1 = L;

    const float4* __restrict__ base =
        reinterpret_cast<const float4*>(xs + (size_t)b * S * D) + t;

    float4 acc = make_float4(0.f, 0.f, 0.f, 0.f);

    int s = s0;
    // Unrolled by 8: 8 independent 16B loads in flight per thread (MLP=8)
    for (; s + 8 <= s1; s += 8) {
        float4 v0 = base[(size_t)(s + 0) * D4];
        float4 v1 = base[(size_t)(s + 1) * D4];
        float4 v2 = base[(size_t)(s + 2) * D4];
        float4 v3 = base[(size_t)(s + 3) * D4];
        float4 v4 = base[(size_t)(s + 4) * D4];
        float4 v5 = base[(size_t)(s + 5) * D4];
        float4 v6 = base[(size_t)(s + 6) * D4];
        float4 v7 = base[(size_t)(s + 7) * D4];
        acc.x += (v0.x + v1.x) + (v2.x + v3.x) + (v4.x + v5.x) + (v6.x + v7.x);
        acc.y += (v0.y + v1.y) + (v2.y + v3.y) + (v4.y + v5.y) + (v6.y + v7.y);
        acc.z += (v0.z + v1.z) + (v2.z + v3.z) + (v4.z + v5.z) + (v6.z + v7.z);
        acc.w += (v0.w + v1.w) + (v2.w + v3.w) + (v4.w + v5.w) + (v6.w + v7.w);
    }
    for (; s < s1; s++) {
        float4 v = base[(size_t)s * D4];
        acc.x += v.x; acc.y += v.y; acc.z += v.z; acc.w += v.w;
    }

    g_partial[(b * SPLIT + sp) * D4 + t] = acc;
}

// Finalize: 128 CTAs (B batches x 8 column-groups), 128 threads each.
// Thread (sp_grp, c): sums 8 splits for one float4 column, then an 8-way
// shared-memory fold produces the final sum for the 16 columns of this group.
__global__ void __launch_bounds__(128)
mean_finalize_kernel(const void* __restrict__ xs_len,
                     float* __restrict__ out) {
    const int b = blockIdx.x >> 3;      // batch
    const int g = blockIdx.x & 7;       // column group: float4 cols [g*16, g*16+16)
    const int t = threadIdx.x;
    const int sp_grp = t >> 4;          // [0,8): which 8-split chunk
    const int c      = t & 15;          // [0,16): float4 column within group

    const int col4 = g * 16 + c;
    const float4* __restrict__ base = &g_partial[(size_t)b * SPLIT * D4 + col4];

    float4 acc = make_float4(0.f, 0.f, 0.f, 0.f);
#pragma unroll
    for (int k = 0; k < 8; k++) {
        float4 v = base[(size_t)(sp_grp * 8 + k) * D4];
        acc.x += v.x; acc.y += v.y; acc.z += v.z; acc.w += v.w;
    }

    __shared__ float4 sm[128];
    sm[t] = acc;
    __syncthreads();

    if (t < 16) {
        float4 r = sm[t];
#pragma unroll
        for (int k = 1; k < 8; k++) {
            float4 v = sm[t + 16 * k];
            r.x += v.x; r.y += v.y; r.z += v.z; r.w += v.w;
        }
        const float inv = 1.0f / (float)decode_len(xs_len, b);
        r.x *= inv; r.y *= inv; r.z *= inv; r.w *= inv;
        reinterpret_cast<float4*>(out)[b * D4 + g * 16 + t] = r;
    }
}

extern "C" void kernel_launch(void* const* d_in, const int* in_sizes, int n_in,
                              void* d_out, int out_size) {
    const float* xs = (const float*)d_in[0];
    const void* xs_len = d_in[1];
    float* out = (float*)d_out;

    dim3 grid1(SPLIT, B);
    mean_partial_kernel<<<grid1, D4>>>(xs, xs_len);
    mean_finalize_kernel<<<B * 8, 128>>>(xs_len, out);
}